// round 16
// baseline (speedup 1.0000x reference)
#include <cuda_runtime.h>
#include <cstdint>

#define HH     480
#define WW     640
#define DIMC   32
#define NB     8
#define HWSZ   (HH * WW)          // 307,200
#define NPIX   (NB * HWSZ)        // 2,457,600
#define TSITES 32                 // sites per accum block (one 8-thread group each)
#define NTILE  (NPIX / TSITES)    // 76,800
#define CAP    16                 // record slots per site (lambda=0.81)

__device__ int g_cur[NPIX];                  // per-site counters (zeroed per call)
__device__ int g_rec[(size_t)NPIX * CAP];    // per-site event lists, 157 MB

__global__ void zero_cur_kernel()
{
    int i = blockIdx.x * blockDim.x + threadIdx.x;
    if (i < NPIX) g_cur[i] = 0;
}

__device__ __forceinline__ void bucket_one(int e, float ex, float ey,
                                           const int* __restrict__ off, int stride)
{
    // jnp.round == round-half-even == __float2int_rn; then clip
    int x = __float2int_rn(ex * (float)WW);
    int y = __float2int_rn(ey * (float)HH);
    x = min(max(x, 0), WW - 1);
    y = min(max(y, 0), HH - 1);

    // searchsorted(offsets, e, side='right') = count of offsets <= e
    // (offset words are L1-hot broadcast loads; stride handles int32 vs int64)
    int b = 0;
#pragma unroll
    for (int i = 0; i < NB; i++)
        b += (e >= __ldg(off + i * stride)) ? 1 : 0;

    int pix  = (b * HH + y) * WW + x;
    int slot = atomicAdd(&g_cur[pix], 1);     // n_conc ~1
    if (slot < CAP)
        g_rec[(size_t)pix * CAP + slot] = e;
}

// 4 events per thread (two float4 event loads): four independent
// atomic->store chains in flight against the ~318cyc ATOMG latency.
// Offset dtype normalization is inlined: int64 LE words = [v0,0,v1,0,...]
// (stride 2, low words), int32 words = [v0,v1,...] (stride 1, o32[1]!=0).
__global__ void bucket_kernel(const float* __restrict__ events,
                              const int* __restrict__ o32, int n)
{
    int t  = blockIdx.x * blockDim.x + threadIdx.x;
    int e0 = 4 * t;
    if (e0 >= n) return;

    int stride = (__ldg(o32 + 1) == 0) ? 2 : 1;

    float4 v0 = __ldg((const float4*)events + 2 * t);
    bucket_one(e0, v0.x, v0.y, o32, stride);
    if (e0 + 1 < n) bucket_one(e0 + 1, v0.z, v0.w, o32, stride);
    if (e0 + 2 < n) {
        float4 v1 = __ldg((const float4*)events + 2 * t + 1);
        bucket_one(e0 + 2, v1.x, v1.y, o32, stride);
        if (e0 + 3 < n) bucket_one(e0 + 3, v1.z, v1.w, o32, stride);
    }
}

// One block per 32-site tile; one 8-THREAD GROUP per site (thread = channel
// quad `part`). Record slots 0..3 arrive as one broadcast int4 (skipped when
// the site is empty); then up to 4 INDEPENDENT feature LDG.128s whose 8 group
// lanes cover one full 128B line (4 wavefronts per warp instruction).
// Register float4 accumulate, no atomics; normalized STS into a 32x33 tile;
// conflict-free transpose; coalesced 128B channel-row writes.
__global__ void __launch_bounds__(256) accum_kernel(const float* __restrict__ feat,
                                                    float* __restrict__ out)
{
    __shared__ float s[TSITES * 33];     // [site*33 + d]

    int tid  = threadIdx.x;              // 0..255
    int grp  = tid >> 3;                 // 0..31 = site within tile
    int part = tid & 7;                  // channel quad
    int pix0 = blockIdx.x * TSITES;
    int site = pix0 + grp;

    int raw = __ldg(&g_cur[site]);       // 8-lane broadcast per group
    int cnt = min(raw, CAP);

    const int* rp = g_rec + (size_t)site * CAP;
    int4 r4 = make_int4(0, 0, 0, 0);
    if (cnt) r4 = __ldg((const int4*)rp);   // slots 0..3, broadcast in group
    int evs[4] = { r4.x, r4.y, r4.z, r4.w };

    float4 acc = make_float4(0.f, 0.f, 0.f, 0.f);

#pragma unroll
    for (int j = 0; j < 4; j++) {
        if (j < cnt) {
            float4 f = __ldg((const float4*)feat + (size_t)evs[j] * 8 + part);
            acc.x += f.x; acc.y += f.y; acc.z += f.z; acc.w += f.w;
        }
    }
    // Rare tail (cnt > 4): ~0.1% of sites.
    for (int j = 4; j < cnt; j++) {
        int e = __ldg(rp + j);
        float4 f = __ldg((const float4*)feat + (size_t)e * 8 + part);
        acc.x += f.x; acc.y += f.y; acc.z += f.z; acc.w += f.w;
    }

    float inv = 1.0f / fmaxf((float)raw, 1.0f);
    float* ps = &s[grp * 33 + part * 4];
    // banks: grp*33 + part*4 + k -> (grp + part*4 + k) mod 32, distinct per warp
    ps[0] = acc.x * inv;
    ps[1] = acc.y * inv;
    ps[2] = acc.z * inv;
    ps[3] = acc.w * inv;
    __syncthreads();

    int bb  = pix0 / HWSZ;
    int rem = pix0 - bb * HWSZ;           // multiple of 32, < HWSZ
    float* obase = out + (size_t)bb * DIMC * HWSZ + rem;

    int w = tid >> 5, lane = tid & 31;    // 8 warps x 4 channels each
#pragma unroll
    for (int i = 0; i < 4; i++) {
        int d = w * 4 + i;
        // smem read: site*33+d -> banks (site + d) mod 32, conflict-free
        obase[(size_t)d * HWSZ + lane] = s[lane * 33 + d];
    }
}

extern "C" void kernel_launch(void* const* d_in, const int* in_sizes, int n_in,
                              void* d_out, int out_size)
{
    const float* events   = (const float*)d_in[0];
    const float* features = (const float*)d_in[1];
    const int*   offs_raw = (const int*)d_in[2];
    int n = in_sizes[0] / 2;

    zero_cur_kernel<<<(NPIX + 255) / 256, 256>>>();               // launch 1

    int nt = (n + 3) / 4;                                          // 4 events/thread
    bucket_kernel<<<(nt + 255) / 256, 256>>>(events, offs_raw, n); // launch 2

    accum_kernel<<<NTILE, 256>>>(features, (float*)d_out);         // launch 3
}

// round 17
// speedup vs baseline: 1.0671x; 1.0671x over previous
#include <cuda_runtime.h>
#include <cstdint>

#define HH     480
#define WW     640
#define DIMC   32
#define NB     8
#define HWSZ   (HH * WW)          // 307,200
#define NPIX   (NB * HWSZ)        // 2,457,600
#define TSITES 32                 // sites per accum block (one 8-thread group each)
#define NTILE  (NPIX / TSITES)    // 76,800
#define SREC   16                 // ints per site: [0]=count, [1..15]=events

// One 64B block per site: counter and event list share a cache line, so the
// bucket pass touches ONE random line per event instead of two.
// Zero-initialized at load; accum restores count=0 for dirty sites each call,
// so "all counts == 0 on entry" holds on every invocation (replay-safe).
__device__ int g_site[(size_t)NPIX * SREC];   // 157 MB

__device__ __forceinline__ void bucket_one(int e, float ex, float ey,
                                           const int off[NB])
{
    // jnp.round == round-half-even == __float2int_rn; then clip
    int x = __float2int_rn(ex * (float)WW);
    int y = __float2int_rn(ey * (float)HH);
    x = min(max(x, 0), WW - 1);
    y = min(max(y, 0), HH - 1);

    // searchsorted(offsets, e, side='right') = count of offsets <= e
    int b = 0;
#pragma unroll
    for (int i = 0; i < NB; i++)
        b += (e >= off[i]) ? 1 : 0;

    int pix   = (b * HH + y) * WW + x;
    int* base = g_site + (size_t)pix * SREC;
    int slot  = atomicAdd(base, 1);           // n_conc ~1
    if (slot < SREC - 1)
        base[1 + slot] = e;                   // same 32B sector for slot<7 (99.9%)
}

// 4 events per thread (two float4 event loads): four independent
// atomic->store chains in flight against the ~318cyc ATOMG latency.
// Offset dtype normalization inlined and HOISTED: offsets land in registers
// once per thread. int64 LE words = [v0,0,v1,0,...] (stride 2), int32 words
// = [v0,v1,...] (o32[1] != 0).
__global__ void bucket_kernel(const float* __restrict__ events,
                              const int* __restrict__ o32, int n)
{
    int t  = blockIdx.x * blockDim.x + threadIdx.x;
    int e0 = 4 * t;
    if (e0 >= n) return;

    int stride = (__ldg(o32 + 1) == 0) ? 2 : 1;
    int off[NB];
#pragma unroll
    for (int i = 0; i < NB; i++)
        off[i] = __ldg(o32 + i * stride);     // 8 L1-hot loads, once per thread

    float4 v0 = __ldg((const float4*)events + 2 * t);
    bucket_one(e0, v0.x, v0.y, off);
    if (e0 + 1 < n) bucket_one(e0 + 1, v0.z, v0.w, off);
    if (e0 + 2 < n) {
        float4 v1 = __ldg((const float4*)events + 2 * t + 1);
        bucket_one(e0 + 2, v1.x, v1.y, off);
        if (e0 + 3 < n) bucket_one(e0 + 3, v1.z, v1.w, off);
    }
}

// One block per 32-site tile; one 8-THREAD GROUP per site (thread = channel
// quad `part`). A single broadcast int4 delivers count + events 0..2 (covers
// 99% of sites); cnt>3 fetches one more int4; cnt>7 rare scalar tail. Up to 4+
// INDEPENDENT feature LDG.128s whose 8 group lanes cover one full 128B line.
// Register float4 accumulate, no atomics; count restored to 0 (dirty sites
// only); normalized STS into a 32x33 tile; conflict-free transpose; coalesced
// 128B channel-row writes.
__global__ void __launch_bounds__(256) accum_kernel(const float* __restrict__ feat,
                                                    float* __restrict__ out)
{
    __shared__ float s[TSITES * 33];     // [site*33 + d]

    int tid  = threadIdx.x;              // 0..255
    int grp  = tid >> 3;                 // 0..31 = site within tile
    int part = tid & 7;                  // channel quad
    int pix0 = blockIdx.x * TSITES;
    int site = pix0 + grp;

    int* base = g_site + (size_t)site * SREC;
    int4 r0 = __ldg((const int4*)base);  // count + events 0..2, group-broadcast
    int raw = r0.x;
    int cnt = min(raw, SREC - 1);

    float4 acc = make_float4(0.f, 0.f, 0.f, 0.f);

    int ev012[3] = { r0.y, r0.z, r0.w };
#pragma unroll
    for (int j = 0; j < 3; j++) {
        if (j < cnt) {
            float4 f = __ldg((const float4*)feat + (size_t)ev012[j] * 8 + part);
            acc.x += f.x; acc.y += f.y; acc.z += f.z; acc.w += f.w;
        }
    }
    if (cnt > 3) {                        // ~1% of sites
        int4 r1 = __ldg((const int4*)base + 1);   // events 3..6
        int ev3456[4] = { r1.x, r1.y, r1.z, r1.w };
#pragma unroll
        for (int j = 0; j < 4; j++) {
            if (3 + j < cnt) {
                float4 f = __ldg((const float4*)feat + (size_t)ev3456[j] * 8 + part);
                acc.x += f.x; acc.y += f.y; acc.z += f.z; acc.w += f.w;
            }
        }
        for (int j = 7; j < cnt; j++) {   // astronomically rare
            int e = __ldg(base + 1 + j);
            float4 f = __ldg((const float4*)feat + (size_t)e * 8 + part);
            acc.x += f.x; acc.y += f.y; acc.z += f.z; acc.w += f.w;
        }
    }

    if (part == 0 && raw != 0)
        base[0] = 0;                      // restore invariant, dirty sites only

    float inv = 1.0f / fmaxf((float)raw, 1.0f);
    float* ps = &s[grp * 33 + part * 4];
    // banks: grp*33 + part*4 + k -> (grp + part*4 + k) mod 32, distinct per warp
    ps[0] = acc.x * inv;
    ps[1] = acc.y * inv;
    ps[2] = acc.z * inv;
    ps[3] = acc.w * inv;
    __syncthreads();

    int bb  = pix0 / HWSZ;
    int rem = pix0 - bb * HWSZ;           // multiple of 32, < HWSZ
    float* obase = out + (size_t)bb * DIMC * HWSZ + rem;

    int w = tid >> 5, lane = tid & 31;    // 8 warps x 4 channels each
#pragma unroll
    for (int i = 0; i < 4; i++) {
        int d = w * 4 + i;
        // smem read: site*33+d -> banks (site + d) mod 32, conflict-free
        obase[(size_t)d * HWSZ + lane] = s[lane * 33 + d];
    }
}

extern "C" void kernel_launch(void* const* d_in, const int* in_sizes, int n_in,
                              void* d_out, int out_size)
{
    const float* events   = (const float*)d_in[0];
    const float* features = (const float*)d_in[1];
    const int*   offs_raw = (const int*)d_in[2];
    int n = in_sizes[0] / 2;

    int nt = (n + 3) / 4;                                          // 4 events/thread
    bucket_kernel<<<(nt + 255) / 256, 256>>>(events, offs_raw, n); // launch 1

    accum_kernel<<<NTILE, 256>>>(features, (float*)d_out);         // launch 2
}